// round 12
// baseline (speedup 1.0000x reference)
#include <cuda_runtime.h>
#include <cstdint>
#include <math.h>

#define BB 32
#define HH 1024
#define VV 32000
#define TT 128
#define KK2 2048          // 2H
#define NGATE 12288       // 4 * 3H

// ---------------- device scratch (static, no allocations) ----------------
__device__ float g_xcat[BB * KK2];            // [b][0:1024]=h_f, [b][1024:2048]=h_b
__device__ float g_gpart[4 * BB * NGATE];     // [part][b][n]  coalesced for gate
__device__ int   g_tok[BB];                   // current decoder tokens
__device__ float g_lse[TT * BB];              // log-sum-exp per (t, b)
__device__ float g_wT[(size_t)2048 * 32000];  // w_out transposed: [(k>>1)][n][k&1]
__device__ float g_wgT[(size_t)4 * 1024 * 3072]; // GRU weights: [g][(k>>1)][n][k&1]
__device__ float4 g_xpair[2 * 8 * 1024];      // [(bs*8+p)*1024+kp2] = (x[b0][k0],x[b1][k0],x[b0][k1],x[b1][k1])

// ---------------- f32x2 helpers ----------------
__device__ __forceinline__ unsigned long long pk2(float a, float b) {
    unsigned long long r;
    asm("mov.b64 %0, {%1, %2};" : "=l"(r) : "f"(a), "f"(b));
    return r;
}
__device__ __forceinline__ float2 upk2(unsigned long long v) {
    float2 f;
    asm("mov.b64 {%0, %1}, %2;" : "=f"(f.x), "=f"(f.y) : "l"(v));
    return f;
}
__device__ __forceinline__ void fma2(unsigned long long& acc, unsigned long long a,
                                     unsigned long long x) {
    asm("fma.rn.f32x2 %0, %1, %2, %0;" : "+l"(acc) : "l"(a), "l"(x));
}

// ---------------- weight transposes (run once per launch, idempotent) ----------------
__global__ void k_transpose_out(const float* __restrict__ w_out) {
    __shared__ float tsm[32][33];
    const int nb = blockIdx.x * 32;
    const int kb = blockIdx.y * 32;
    const int tid = threadIdx.x;
    for (int i = tid; i < 1024; i += 256) {
        int kl = i & 31, nl = i >> 5;
        tsm[nl][kl] = w_out[(size_t)(nb + nl) * 2048 + kb + kl];
    }
    __syncthreads();
    float2* outp = (float2*)g_wT;
    for (int i = tid; i < 512; i += 256) {
        int nl = i & 31, kpl = i >> 5;
        outp[(size_t)((kb >> 1) + kpl) * 32000 + nb + nl] =
            make_float2(tsm[nl][2 * kpl], tsm[nl][2 * kpl + 1]);
    }
}

__global__ void k_transpose_gru(const float* __restrict__ w_ih_f, const float* __restrict__ w_hh_f,
                                const float* __restrict__ w_ih_b, const float* __restrict__ w_hh_b) {
    __shared__ float tsm[32][33];
    const int nb = blockIdx.x * 32;  // 0..3071
    const int kb = blockIdx.y * 32;  // 0..1023
    const int g = blockIdx.z;        // 0..3
    const float* W = (g == 0) ? w_ih_f : (g == 1) ? w_hh_f : (g == 2) ? w_ih_b : w_hh_b;
    const int tid = threadIdx.x;
    for (int i = tid; i < 1024; i += 256) {
        int kl = i & 31, nl = i >> 5;
        tsm[nl][kl] = W[(size_t)(nb + nl) * 1024 + kb + kl];
    }
    __syncthreads();
    float2* outp = (float2*)g_wgT + (size_t)g * 512 * 3072;
    for (int i = tid; i < 512; i += 256) {
        int nl = i & 31, kpl = i >> 5;
        outp[(size_t)((kb >> 1) + kpl) * 3072 + nb + nl] =
            make_float2(tsm[nl][2 * kpl], tsm[nl][2 * kpl + 1]);
    }
}

// ---------------- init: hidden -> g_xcat, tokens (int32/int64 autodetect) ----------------
__global__ void k_init(const int* __restrict__ toks_raw, const float* __restrict__ hidden) {
    int idx = blockIdx.x * blockDim.x + threadIdx.x;
    if (idx < 2 * BB * HH) {
        int c = idx / (BB * HH);
        int rem = idx - c * (BB * HH);
        int b = rem / HH;
        int j = rem - b * HH;
        g_xcat[b * KK2 + c * HH + j] = hidden[idx];
    } else if (idx < 2 * BB * HH + BB) {
        int b = idx - 2 * BB * HH;
        bool is64 = true;
        for (int i = 1; i < 32; i += 2)
            if (toks_raw[i] != 0) is64 = false;
        g_tok[b] = is64 ? toks_raw[2 * b] : toks_raw[b];
    }
}

// ---------------- GRU GEMM (embedding fused, batch-split) ----------------
// Grid (48 n-tiles, 4 k-parts, 2 batch-halves), 256 thr, occ 3.  [verified]
__global__ void __launch_bounds__(256, 3)
k_gru_gemm(const float* __restrict__ emb) {
    __shared__ float2 xs[2][8][128];  // 16 KB; reused for combine + tile

    const int tile = blockIdx.x;   // 0..47
    const int kpart = blockIdx.y;  // 0..3
    const int bs = blockIdx.z;     // 0..1 : batches [bs*16, bs*16+16)
    const int n_base = tile * 256;
    const int g = n_base / 3072;   // 0:ih_f 1:hh_f 2:ih_b 3:hh_b
    const int wrow_base = n_base % 3072;

    const int tid = threadIdx.x;
    const int w = tid >> 5, lane = tid & 31;
    const int ks = w >> 2, wn = w & 3;

    for (int i = tid; i < 2 * 8 * 128; i += 256) {
        int s = i >> 10;
        int rem = i & 1023;
        int p = rem >> 7;
        int k = rem & 127;
        int kg = kpart * 256 + s * 128 + k;
        int b0 = bs * 16 + 2 * p, b1 = b0 + 1;
        float v0, v1;
        if (g & 1) {
            int half = g >> 1;
            v0 = g_xcat[b0 * KK2 + half * HH + kg];
            v1 = g_xcat[b1 * KK2 + half * HH + kg];
        } else {
            v0 = emb[(size_t)g_tok[b0] * HH + kg];
            v1 = emb[(size_t)g_tok[b1] * HH + kg];
        }
        xs[s][p][k] = make_float2(v0, v1);
    }
    __syncthreads();

    const int n_local0 = wn * 64 + lane;
    unsigned long long acc[2][8];
#pragma unroll
    for (int i2 = 0; i2 < 2; ++i2)
#pragma unroll
        for (int p = 0; p < 8; ++p) acc[i2][p] = 0ULL;

    const float2* wp = (const float2*)g_wgT + (size_t)g * 512 * 3072 +
                       (size_t)(kpart * 128 + ks * 64) * 3072 + wrow_base + n_local0;
#pragma unroll 4
    for (int kp = 0; kp < 64; ++kp) {
        float2 a0 = wp[0];
        float2 a1 = wp[32];
        wp += 3072;
        unsigned long long w00 = pk2(a0.x, a0.x);
        unsigned long long w01 = pk2(a0.y, a0.y);
        unsigned long long w10 = pk2(a1.x, a1.x);
        unsigned long long w11 = pk2(a1.y, a1.y);
#pragma unroll
        for (int p = 0; p < 8; ++p) {
            ulonglong2 xv = *(const ulonglong2*)&xs[ks][p][2 * kp];
            fma2(acc[0][p], w00, xv.x);
            fma2(acc[0][p], w01, xv.y);
            fma2(acc[1][p], w10, xv.x);
            fma2(acc[1][p], w11, xv.y);
        }
    }

    __syncthreads();
    float2* csm = (float2*)xs;  // [16][128]
    if (tid >= 128) {
        int u = tid - 128;
#pragma unroll
        for (int i2 = 0; i2 < 2; ++i2)
#pragma unroll
            for (int p = 0; p < 8; ++p)
                csm[(i2 * 8 + p) * 128 + u] = upk2(acc[i2][p]);
    }
    __syncthreads();
    float2 res[2][8];
    if (tid < 128) {
#pragma unroll
        for (int i2 = 0; i2 < 2; ++i2)
#pragma unroll
            for (int p = 0; p < 8; ++p) {
                float2 a = upk2(acc[i2][p]);
                float2 c = csm[(i2 * 8 + p) * 128 + tid];
                res[i2][p] = make_float2(a.x + c.x, a.y + c.y);
            }
    }
    __syncthreads();
    float* tilep = (float*)xs;  // [16][256]
    if (tid < 128) {
#pragma unroll
        for (int i2 = 0; i2 < 2; ++i2) {
            int nl = n_local0 + i2 * 32;
#pragma unroll
            for (int p = 0; p < 8; ++p) {
                tilep[(2 * p) * 256 + nl] = res[i2][p].x;
                tilep[(2 * p + 1) * 256 + nl] = res[i2][p].y;
            }
        }
    }
    __syncthreads();
    float* dst = g_gpart + (size_t)kpart * BB * NGATE;
    for (int i = tid; i < 16 * 256; i += 256) {
        int bl = i >> 8;
        int nl = i & 255;
        dst[(size_t)(bs * 16 + bl) * NGATE + n_base + nl] = tilep[i];
    }
}

// ---------------- gate combine: update h_f / h_b in g_xcat ----------------
__device__ __forceinline__ float sigf(float x) { return 1.0f / (1.0f + expf(-x)); }
__device__ __forceinline__ float tanh_acc(float x) {
    float ax = fabsf(x);
    float t = expf(-2.0f * ax);
    float r = (1.0f - t) / (1.0f + t);
    return copysignf(r, x);
}
__device__ __forceinline__ float gsum(int row, int b) {
    return g_gpart[(size_t)0 * BB * NGATE + (size_t)b * NGATE + row] +
           g_gpart[(size_t)1 * BB * NGATE + (size_t)b * NGATE + row] +
           g_gpart[(size_t)2 * BB * NGATE + (size_t)b * NGATE + row] +
           g_gpart[(size_t)3 * BB * NGATE + (size_t)b * NGATE + row];
}
__global__ void k_gate(const float* __restrict__ b_ih_f, const float* __restrict__ b_hh_f,
                       const float* __restrict__ b_ih_b, const float* __restrict__ b_hh_b) {
    int idx = blockIdx.x * blockDim.x + threadIdx.x;  // 65536
    int c = idx >> 15;
    int b = (idx >> 10) & 31;
    int j = idx & 1023;
    const float* bih = c ? b_ih_b : b_ih_f;
    const float* bhh = c ? b_hh_b : b_hh_f;
    int base = c * 6144;
    float i_r = gsum(base + j, b)        + bih[j];
    float i_z = gsum(base + 1024 + j, b) + bih[1024 + j];
    float i_n = gsum(base + 2048 + j, b) + bih[2048 + j];
    float h_r = gsum(base + 3072 + j, b) + bhh[j];
    float h_z = gsum(base + 4096 + j, b) + bhh[1024 + j];
    float h_n = gsum(base + 5120 + j, b) + bhh[2048 + j];
    float r = sigf(i_r + h_r);
    float z = sigf(i_z + h_z);
    float nn = tanh_acc(i_n + r * h_n);
    float hp = g_xcat[b * KK2 + c * HH + j];
    g_xcat[b * KK2 + c * HH + j] = (1.0f - z) * nn + z * hp;
}

// ---------------- pack x into broadcast-friendly quads for the logits GEMM ----------------
// g_xpair[(bs*8+p)*1024 + kp2] = (x[b0][2kp2], x[b1][2kp2], x[b0][2kp2+1], x[b1][2kp2+1])
__global__ void k_pack() {
    int idx = blockIdx.x * 256 + threadIdx.x;  // 0..16383
    int bs = idx >> 13;
    int rem = idx & 8191;
    int p = rem >> 10;
    int kp2 = rem & 1023;
    int b0 = bs * 16 + 2 * p, b1 = b0 + 1;
    float2 v0 = *(const float2*)&g_xcat[b0 * KK2 + 2 * kp2];
    float2 v1 = *(const float2*)&g_xcat[b1 * KK2 + 2 * kp2];
    g_xpair[idx] = make_float4(v0.x, v1.x, v0.y, v1.y);
}

// ---------------- logits GEMM: no smem in mainloop, x via L1-broadcast LDG ----------------
// Grid (125 n-tiles of 256, 2 batch-halves), 256 thr, occ 2.
__global__ void __launch_bounds__(256, 2)
k_logits(const float* __restrict__ b_out, float* __restrict__ outp /* d_out + t*V */) {
    __shared__ float2 csm[2048];  // 16 KB, epilogue only

    const int n_base = blockIdx.x * 256;
    const int bs = blockIdx.y;  // 0..1 : batches [bs*16, bs*16+16)
    const int tid = threadIdx.x;
    const int w = tid >> 5, lane = tid & 31;
    const int ks = w >> 2, wn = w & 3;   // ks: K half, wn: 64-wide n group
    const int n_local0 = wn * 64 + lane;

    unsigned long long acc[2][8];
#pragma unroll
    for (int i2 = 0; i2 < 2; ++i2)
#pragma unroll
        for (int p = 0; p < 8; ++p) acc[i2][p] = 0ULL;

    // x quads: warp-uniform addresses -> L1-resident broadcast stream
    const ulonglong2* xp = (const ulonglong2*)g_xpair + (size_t)bs * 8192 + ks * 512;
    const float2* wp = (const float2*)g_wT + (size_t)(ks * 512) * 32000 + n_base + n_local0;

#pragma unroll 4
    for (int kp2 = 0; kp2 < 512; ++kp2) {
        float2 a0 = wp[0];
        float2 a1 = wp[32];
        wp += 32000;
        unsigned long long w00 = pk2(a0.x, a0.x);
        unsigned long long w01 = pk2(a0.y, a0.y);
        unsigned long long w10 = pk2(a1.x, a1.x);
        unsigned long long w11 = pk2(a1.y, a1.y);
#pragma unroll
        for (int p = 0; p < 8; ++p) {
            ulonglong2 xv = xp[p * 1024 + kp2];
            fma2(acc[0][p], w00, xv.x);
            fma2(acc[0][p], w01, xv.y);
            fma2(acc[1][p], w10, xv.x);
            fma2(acc[1][p], w11, xv.y);
        }
    }

    // combine the two K halves (upper warps -> smem, lower warps add)
    __syncthreads();
    if (tid >= 128) {
        int u = tid - 128;
#pragma unroll
        for (int i2 = 0; i2 < 2; ++i2)
#pragma unroll
            for (int p = 0; p < 8; ++p)
                csm[(i2 * 8 + p) * 128 + u] = upk2(acc[i2][p]);
    }
    __syncthreads();
    float2 res[2][8];
    if (tid < 128) {
#pragma unroll
        for (int i2 = 0; i2 < 2; ++i2)
#pragma unroll
            for (int p = 0; p < 8; ++p) {
                float2 a = upk2(acc[i2][p]);
                float2 c = csm[(i2 * 8 + p) * 128 + tid];
                res[i2][p] = make_float2(a.x + c.x, a.y + c.y);
            }
    }
    __syncthreads();
    float* tilep = (float*)csm;  // [16][256]
    if (tid < 128) {
#pragma unroll
        for (int i2 = 0; i2 < 2; ++i2) {
            int nl = n_local0 + i2 * 32;
#pragma unroll
            for (int p = 0; p < 8; ++p) {
                tilep[(2 * p) * 256 + nl] = res[i2][p].x;
                tilep[(2 * p + 1) * 256 + nl] = res[i2][p].y;
            }
        }
    }
    __syncthreads();
    for (int i = tid; i < 16 * 256; i += 256) {
        int bl = i >> 8;
        int nl = i & 255;
        int n = n_base + nl;
        outp[(size_t)(bs * 16 + bl) * ((size_t)TT * VV) + n] = tilep[i] + b_out[n];
    }
}

// ---------------- per-b online (max, argmax, sum) -> g_lse, g_tok ----------------
__global__ void k_smreduce(const float* __restrict__ outp /* d_out + t*V */, int t) {
    const int b = blockIdx.x;
    const int tid = threadIdx.x;  // 1024
    const float* r = outp + (size_t)b * ((size_t)TT * VV);

    float m = -3.4e38f;
    float s = 0.0f;
    int am = 0;
    for (int v = tid; v < VV; v += 1024) {
        float x = r[v];
        if (x > m) {
            s = s * expf(m - x) + 1.0f;
            m = x;
            am = v;
        } else {
            s += expf(x - m);
        }
    }
    for (int off = 16; off > 0; off >>= 1) {
        float om = __shfl_down_sync(0xFFFFFFFFu, m, off);
        float os = __shfl_down_sync(0xFFFFFFFFu, s, off);
        int oa = __shfl_down_sync(0xFFFFFFFFu, am, off);
        if (om > m || (om == m && oa < am)) {
            s = os + s * expf(m - om);
            m = om;
            am = oa;
        } else {
            s = s + os * expf(om - m);
        }
    }
    __shared__ float smm[32], sms[32];
    __shared__ int sma[32];
    int wid = tid >> 5, lid = tid & 31;
    if (lid == 0) { smm[wid] = m; sms[wid] = s; sma[wid] = am; }
    __syncthreads();
    if (wid == 0) {
        m = smm[lid]; s = sms[lid]; am = sma[lid];
        for (int off = 16; off > 0; off >>= 1) {
            float om = __shfl_down_sync(0xFFFFFFFFu, m, off);
            float os = __shfl_down_sync(0xFFFFFFFFu, s, off);
            int oa = __shfl_down_sync(0xFFFFFFFFu, am, off);
            if (om > m || (om == m && oa < am)) {
                s = os + s * expf(m - om);
                m = om;
                am = oa;
            } else {
                s = s + os * expf(om - m);
            }
        }
        if (lid == 0) {
            g_lse[t * BB + b] = m + logf(s);
            g_tok[b] = am;
        }
    }
}

// ---------------- final: subtract lse over the whole output ----------------
__global__ void k_norm(float* __restrict__ out) {
    size_t i = (size_t)blockIdx.x * 256 + threadIdx.x;  // float4 index
    const size_t per_b = (size_t)TT * VV / 4;  // 1,024,000
    if (i >= (size_t)BB * per_b) return;
    int b = (int)(i / per_b);
    size_t rem = i - (size_t)b * per_b;
    int t = (int)(rem / (VV / 4));
    float l = g_lse[t * BB + b];
    float4* p = (float4*)out + i;
    float4 v = *p;
    v.x -= l; v.y -= l; v.z -= l; v.w -= l;
    *p = v;
}

// ---------------- host ----------------
extern "C" void kernel_launch(void* const* d_in, const int* in_sizes, int n_in,
                              void* d_out, int out_size) {
    const int* toks = (const int*)d_in[0];
    const float* hidden = (const float*)d_in[1];
    const float* emb = (const float*)d_in[2];
    const float* w_ih_f = (const float*)d_in[3];
    const float* w_hh_f = (const float*)d_in[4];
    const float* b_ih_f = (const float*)d_in[5];
    const float* b_hh_f = (const float*)d_in[6];
    const float* w_ih_b = (const float*)d_in[7];
    const float* w_hh_b = (const float*)d_in[8];
    const float* b_ih_b = (const float*)d_in[9];
    const float* b_hh_b = (const float*)d_in[10];
    const float* w_out = (const float*)d_in[11];
    const float* b_out = (const float*)d_in[12];
    float* out = (float*)d_out;

    (void)in_sizes; (void)n_in; (void)out_size;

    k_transpose_out<<<dim3(1000, 64), 256>>>(w_out);
    k_transpose_gru<<<dim3(96, 32, 4), 256>>>(w_ih_f, w_hh_f, w_ih_b, w_hh_b);
    k_init<<<(2 * BB * HH + BB + 255) / 256, 256>>>(toks, hidden);

    for (int t = 0; t < TT; ++t) {
        k_gru_gemm<<<dim3(48, 4, 2), 256>>>(emb);
        k_gate<<<(2 * BB * HH) / 256, 256>>>(b_ih_f, b_hh_f, b_ih_b, b_hh_b);
        k_pack<<<64, 256>>>();
        k_logits<<<dim3(125, 2), 256>>>(b_out, out + (size_t)t * VV);
        k_smreduce<<<BB, 1024>>>(out + (size_t)t * VV, t);
    }
    k_norm<<<128000, 256>>>(out);
}

// round 14
// speedup vs baseline: 1.1684x; 1.1684x over previous
#include <cuda_runtime.h>
#include <cstdint>
#include <math.h>

#define BB 32
#define HH 1024
#define VV 32000
#define TT 128
#define KK2 2048          // 2H
#define NGATE 12288       // 4 * 3H

// ---------------- device scratch (static, no allocations) ----------------
__device__ float g_xcat[BB * KK2];            // [b][0:1024]=h_f, [b][1024:2048]=h_b
__device__ float g_gpart[4 * BB * NGATE];     // [part][b][n]  coalesced for gate
__device__ int   g_tok[BB];                   // current decoder tokens
__device__ float g_lse[TT * BB];              // log-sum-exp per (t, b)
__device__ float g_wT[(size_t)2048 * 32000];  // w_out transposed: [(k>>1)][n][k&1]
__device__ float g_wgT[(size_t)4 * 1024 * 3072]; // GRU weights: [g][(k>>1)][n][k&1]

// ---------------- f32x2 helpers ----------------
__device__ __forceinline__ unsigned long long pk2(float a, float b) {
    unsigned long long r;
    asm("mov.b64 %0, {%1, %2};" : "=l"(r) : "f"(a), "f"(b));
    return r;
}
__device__ __forceinline__ float2 upk2(unsigned long long v) {
    float2 f;
    asm("mov.b64 {%0, %1}, %2;" : "=f"(f.x), "=f"(f.y) : "l"(v));
    return f;
}
__device__ __forceinline__ void fma2(unsigned long long& acc, unsigned long long a,
                                     unsigned long long x) {
    asm("fma.rn.f32x2 %0, %1, %2, %0;" : "+l"(acc) : "l"(a), "l"(x));
}

// ---------------- weight transposes (run once per launch, idempotent) ----------------
__global__ void k_transpose_out(const float* __restrict__ w_out) {
    __shared__ float tsm[32][33];
    const int nb = blockIdx.x * 32;
    const int kb = blockIdx.y * 32;
    const int tid = threadIdx.x;
    for (int i = tid; i < 1024; i += 256) {
        int kl = i & 31, nl = i >> 5;
        tsm[nl][kl] = w_out[(size_t)(nb + nl) * 2048 + kb + kl];
    }
    __syncthreads();
    float2* outp = (float2*)g_wT;
    for (int i = tid; i < 512; i += 256) {
        int nl = i & 31, kpl = i >> 5;
        outp[(size_t)((kb >> 1) + kpl) * 32000 + nb + nl] =
            make_float2(tsm[nl][2 * kpl], tsm[nl][2 * kpl + 1]);
    }
}

__global__ void k_transpose_gru(const float* __restrict__ w_ih_f, const float* __restrict__ w_hh_f,
                                const float* __restrict__ w_ih_b, const float* __restrict__ w_hh_b) {
    __shared__ float tsm[32][33];
    const int nb = blockIdx.x * 32;  // 0..3071
    const int kb = blockIdx.y * 32;  // 0..1023
    const int g = blockIdx.z;        // 0..3
    const float* W = (g == 0) ? w_ih_f : (g == 1) ? w_hh_f : (g == 2) ? w_ih_b : w_hh_b;
    const int tid = threadIdx.x;
    for (int i = tid; i < 1024; i += 256) {
        int kl = i & 31, nl = i >> 5;
        tsm[nl][kl] = W[(size_t)(nb + nl) * 1024 + kb + kl];
    }
    __syncthreads();
    float2* outp = (float2*)g_wgT + (size_t)g * 512 * 3072;
    for (int i = tid; i < 512; i += 256) {
        int nl = i & 31, kpl = i >> 5;
        outp[(size_t)((kb >> 1) + kpl) * 3072 + nb + nl] =
            make_float2(tsm[nl][2 * kpl], tsm[nl][2 * kpl + 1]);
    }
}

// ---------------- init: hidden -> g_xcat, tokens (int32/int64 autodetect) ----------------
__global__ void k_init(const int* __restrict__ toks_raw, const float* __restrict__ hidden) {
    int idx = blockIdx.x * blockDim.x + threadIdx.x;
    if (idx < 2 * BB * HH) {
        int c = idx / (BB * HH);
        int rem = idx - c * (BB * HH);
        int b = rem / HH;
        int j = rem - b * HH;
        g_xcat[b * KK2 + c * HH + j] = hidden[idx];
    } else if (idx < 2 * BB * HH + BB) {
        int b = idx - 2 * BB * HH;
        bool is64 = true;
        for (int i = 1; i < 32; i += 2)
            if (toks_raw[i] != 0) is64 = false;
        g_tok[b] = is64 ? toks_raw[2 * b] : toks_raw[b];
    }
}

// ---------------- GRU GEMM (embedding fused, batch-split) ----------------
// Grid (48 n-tiles, 4 k-parts, 2 batch-halves), 256 thr, occ 3.  [verified]
__global__ void __launch_bounds__(256, 3)
k_gru_gemm(const float* __restrict__ emb) {
    __shared__ float2 xs[2][8][128];  // 16 KB; reused for combine + tile

    const int tile = blockIdx.x;   // 0..47
    const int kpart = blockIdx.y;  // 0..3
    const int bs = blockIdx.z;     // 0..1 : batches [bs*16, bs*16+16)
    const int n_base = tile * 256;
    const int g = n_base / 3072;   // 0:ih_f 1:hh_f 2:ih_b 3:hh_b
    const int wrow_base = n_base % 3072;

    const int tid = threadIdx.x;
    const int w = tid >> 5, lane = tid & 31;
    const int ks = w >> 2, wn = w & 3;

    for (int i = tid; i < 2 * 8 * 128; i += 256) {
        int s = i >> 10;
        int rem = i & 1023;
        int p = rem >> 7;
        int k = rem & 127;
        int kg = kpart * 256 + s * 128 + k;
        int b0 = bs * 16 + 2 * p, b1 = b0 + 1;
        float v0, v1;
        if (g & 1) {
            int half = g >> 1;
            v0 = g_xcat[b0 * KK2 + half * HH + kg];
            v1 = g_xcat[b1 * KK2 + half * HH + kg];
        } else {
            v0 = emb[(size_t)g_tok[b0] * HH + kg];
            v1 = emb[(size_t)g_tok[b1] * HH + kg];
        }
        xs[s][p][k] = make_float2(v0, v1);
    }
    __syncthreads();

    const int n_local0 = wn * 64 + lane;
    unsigned long long acc[2][8];
#pragma unroll
    for (int i2 = 0; i2 < 2; ++i2)
#pragma unroll
        for (int p = 0; p < 8; ++p) acc[i2][p] = 0ULL;

    const float2* wp = (const float2*)g_wgT + (size_t)g * 512 * 3072 +
                       (size_t)(kpart * 128 + ks * 64) * 3072 + wrow_base + n_local0;
#pragma unroll 4
    for (int kp = 0; kp < 64; ++kp) {
        float2 a0 = wp[0];
        float2 a1 = wp[32];
        wp += 3072;
        unsigned long long w00 = pk2(a0.x, a0.x);
        unsigned long long w01 = pk2(a0.y, a0.y);
        unsigned long long w10 = pk2(a1.x, a1.x);
        unsigned long long w11 = pk2(a1.y, a1.y);
#pragma unroll
        for (int p = 0; p < 8; ++p) {
            ulonglong2 xv = *(const ulonglong2*)&xs[ks][p][2 * kp];
            fma2(acc[0][p], w00, xv.x);
            fma2(acc[0][p], w01, xv.y);
            fma2(acc[1][p], w10, xv.x);
            fma2(acc[1][p], w11, xv.y);
        }
    }

    __syncthreads();
    float2* csm = (float2*)xs;  // [16][128]
    if (tid >= 128) {
        int u = tid - 128;
#pragma unroll
        for (int i2 = 0; i2 < 2; ++i2)
#pragma unroll
            for (int p = 0; p < 8; ++p)
                csm[(i2 * 8 + p) * 128 + u] = upk2(acc[i2][p]);
    }
    __syncthreads();
    float2 res[2][8];
    if (tid < 128) {
#pragma unroll
        for (int i2 = 0; i2 < 2; ++i2)
#pragma unroll
            for (int p = 0; p < 8; ++p) {
                float2 a = upk2(acc[i2][p]);
                float2 c = csm[(i2 * 8 + p) * 128 + tid];
                res[i2][p] = make_float2(a.x + c.x, a.y + c.y);
            }
    }
    __syncthreads();
    float* tilep = (float*)xs;  // [16][256]
    if (tid < 128) {
#pragma unroll
        for (int i2 = 0; i2 < 2; ++i2) {
            int nl = n_local0 + i2 * 32;
#pragma unroll
            for (int p = 0; p < 8; ++p) {
                tilep[(2 * p) * 256 + nl] = res[i2][p].x;
                tilep[(2 * p + 1) * 256 + nl] = res[i2][p].y;
            }
        }
    }
    __syncthreads();
    float* dst = g_gpart + (size_t)kpart * BB * NGATE;
    for (int i = tid; i < 16 * 256; i += 256) {
        int bl = i >> 8;
        int nl = i & 255;
        dst[(size_t)(bs * 16 + bl) * NGATE + n_base + nl] = tilep[i];
    }
}

// ---------------- gate combine: update h_f / h_b in g_xcat ----------------
__device__ __forceinline__ float sigf(float x) { return 1.0f / (1.0f + expf(-x)); }
__device__ __forceinline__ float tanh_acc(float x) {
    float ax = fabsf(x);
    float t = expf(-2.0f * ax);
    float r = (1.0f - t) / (1.0f + t);
    return copysignf(r, x);
}
__device__ __forceinline__ float gsum(int row, int b) {
    return g_gpart[(size_t)0 * BB * NGATE + (size_t)b * NGATE + row] +
           g_gpart[(size_t)1 * BB * NGATE + (size_t)b * NGATE + row] +
           g_gpart[(size_t)2 * BB * NGATE + (size_t)b * NGATE + row] +
           g_gpart[(size_t)3 * BB * NGATE + (size_t)b * NGATE + row];
}
__global__ void k_gate(const float* __restrict__ b_ih_f, const float* __restrict__ b_hh_f,
                       const float* __restrict__ b_ih_b, const float* __restrict__ b_hh_b) {
    int idx = blockIdx.x * blockDim.x + threadIdx.x;  // 65536
    int c = idx >> 15;
    int b = (idx >> 10) & 31;
    int j = idx & 1023;
    const float* bih = c ? b_ih_b : b_ih_f;
    const float* bhh = c ? b_hh_b : b_hh_f;
    int base = c * 6144;
    float i_r = gsum(base + j, b)        + bih[j];
    float i_z = gsum(base + 1024 + j, b) + bih[1024 + j];
    float i_n = gsum(base + 2048 + j, b) + bih[2048 + j];
    float h_r = gsum(base + 3072 + j, b) + bhh[j];
    float h_z = gsum(base + 4096 + j, b) + bhh[1024 + j];
    float h_n = gsum(base + 5120 + j, b) + bhh[2048 + j];
    float r = sigf(i_r + h_r);
    float z = sigf(i_z + h_z);
    float nn = tanh_acc(i_n + r * h_n);
    float hp = g_xcat[b * KK2 + c * HH + j];
    g_xcat[b * KK2 + c * HH + j] = (1.0f - z) * nn + z * hp;
}

// ---------------- logits GEMM: 125 blocks x 512 threads, all batches per block ----------------
// Warp (bsg, ks, wn): 16 batches (bsg half) x 64 n x 1024 k (ks half).
// Double-buffered 64-k staging chunks; one sync per chunk; balanced 1 block/SM.
__global__ void __launch_bounds__(512, 1)
k_logits(const float* __restrict__ b_out, float* __restrict__ outp /* d_out + t*V */) {
    __shared__ float2 xs[2][2][2][8][64];  // [buf][khalf][bsg][p][k] = 32 KB

    const int n_base = blockIdx.x * 256;
    const int tid = threadIdx.x;
    const int w = tid >> 5, lane = tid & 31;
    const int bsg = w >> 3;          // batch half
    const int ks = (w >> 2) & 1;     // K half
    const int wn = w & 3;            // 64-wide n group
    const int n_local0 = wn * 64 + lane;

    unsigned long long acc[2][8];
#pragma unroll
    for (int i2 = 0; i2 < 2; ++i2)
#pragma unroll
        for (int p = 0; p < 8; ++p) acc[i2][p] = 0ULL;

    // prologue: stage chunk 0
#pragma unroll
    for (int q = 0; q < 4; ++q) {
        int f = tid + 512 * q;
        int k = f & 63, p = (f >> 6) & 7, bsx = (f >> 9) & 1, s = f >> 10;
        int kg = s * 1024 + k;
        int b0 = bsx * 16 + 2 * p;
        xs[0][s][bsx][p][k] = make_float2(g_xcat[b0 * KK2 + kg],
                                          g_xcat[(b0 + 1) * KK2 + kg]);
    }
    __syncthreads();

    const float2* wp = (const float2*)g_wT + (size_t)(ks * 512) * 32000 + n_base + n_local0;

    for (int c = 0; c < 16; ++c) {
        // prefetch next chunk into registers (LDGs issue before compute)
        float va[4], vb[4];
        if (c < 15) {
#pragma unroll
            for (int q = 0; q < 4; ++q) {
                int f = tid + 512 * q;
                int k = f & 63, p = (f >> 6) & 7, bsx = (f >> 9) & 1, s = f >> 10;
                int kg = s * 1024 + (c + 1) * 64 + k;
                int b0 = bsx * 16 + 2 * p;
                va[q] = g_xcat[b0 * KK2 + kg];
                vb[q] = g_xcat[(b0 + 1) * KK2 + kg];
            }
        }
        // compute current chunk from smem broadcast
        const int buf = c & 1;
#pragma unroll 4
        for (int kp = 0; kp < 32; ++kp) {
            float2 a0 = wp[0];
            float2 a1 = wp[32];
            wp += 32000;
            unsigned long long w00 = pk2(a0.x, a0.x);
            unsigned long long w01 = pk2(a0.y, a0.y);
            unsigned long long w10 = pk2(a1.x, a1.x);
            unsigned long long w11 = pk2(a1.y, a1.y);
#pragma unroll
            for (int p = 0; p < 8; ++p) {
                ulonglong2 xv = *(const ulonglong2*)&xs[buf][ks][bsg][p][2 * kp];
                fma2(acc[0][p], w00, xv.x);
                fma2(acc[0][p], w01, xv.y);
                fma2(acc[1][p], w10, xv.x);
                fma2(acc[1][p], w11, xv.y);
            }
        }
        // store prefetched data into the other buffer
        if (c < 15) {
#pragma unroll
            for (int q = 0; q < 4; ++q) {
                int f = tid + 512 * q;
                int k = f & 63, p = (f >> 6) & 7, bsx = (f >> 9) & 1, s = f >> 10;
                xs[(c + 1) & 1][s][bsx][p][k] = make_float2(va[q], vb[q]);
            }
        }
        __syncthreads();
    }

    // epilogue: two independent bs-groups in disjoint 16 KB regions
    const int gtid = tid & 255;
    float2* csm = (float2*)xs + bsg * 2048;  // [16][128] float2
    if (gtid >= 128) {
        int u = gtid - 128;  // ks==1 warps
#pragma unroll
        for (int i2 = 0; i2 < 2; ++i2)
#pragma unroll
            for (int p = 0; p < 8; ++p)
                csm[(i2 * 8 + p) * 128 + u] = upk2(acc[i2][p]);
    }
    __syncthreads();
    float2 res[2][8];
    if (gtid < 128) {
#pragma unroll
        for (int i2 = 0; i2 < 2; ++i2)
#pragma unroll
            for (int p = 0; p < 8; ++p) {
                float2 a = upk2(acc[i2][p]);
                float2 c2 = csm[(i2 * 8 + p) * 128 + gtid];
                res[i2][p] = make_float2(a.x + c2.x, a.y + c2.y);
            }
    }
    __syncthreads();
    float* tilep = (float*)csm;  // [16][256]
    if (gtid < 128) {
#pragma unroll
        for (int i2 = 0; i2 < 2; ++i2) {
            int nl = n_local0 + i2 * 32;
#pragma unroll
            for (int p = 0; p < 8; ++p) {
                tilep[(2 * p) * 256 + nl] = res[i2][p].x;
                tilep[(2 * p + 1) * 256 + nl] = res[i2][p].y;
            }
        }
    }
    __syncthreads();
    for (int i = gtid; i < 16 * 256; i += 256) {
        int bl = i >> 8;
        int nl = i & 255;
        int n = n_base + nl;
        outp[(size_t)(bsg * 16 + bl) * ((size_t)TT * VV) + n] = tilep[i] + b_out[n];
    }
}

// ---------------- per-b online (max, argmax, sum) -> g_lse, g_tok ----------------
__global__ void k_smreduce(const float* __restrict__ outp /* d_out + t*V */, int t) {
    const int b = blockIdx.x;
    const int tid = threadIdx.x;  // 1024
    const float* r = outp + (size_t)b * ((size_t)TT * VV);

    float m = -3.4e38f;
    float s = 0.0f;
    int am = 0;
    for (int v = tid; v < VV; v += 1024) {
        float x = r[v];
        if (x > m) {
            s = s * expf(m - x) + 1.0f;
            m = x;
            am = v;
        } else {
            s += expf(x - m);
        }
    }
    for (int off = 16; off > 0; off >>= 1) {
        float om = __shfl_down_sync(0xFFFFFFFFu, m, off);
        float os = __shfl_down_sync(0xFFFFFFFFu, s, off);
        int oa = __shfl_down_sync(0xFFFFFFFFu, am, off);
        if (om > m || (om == m && oa < am)) {
            s = os + s * expf(m - om);
            m = om;
            am = oa;
        } else {
            s = s + os * expf(om - m);
        }
    }
    __shared__ float smm[32], sms[32];
    __shared__ int sma[32];
    int wid = tid >> 5, lid = tid & 31;
    if (lid == 0) { smm[wid] = m; sms[wid] = s; sma[wid] = am; }
    __syncthreads();
    if (wid == 0) {
        m = smm[lid]; s = sms[lid]; am = sma[lid];
        for (int off = 16; off > 0; off >>= 1) {
            float om = __shfl_down_sync(0xFFFFFFFFu, m, off);
            float os = __shfl_down_sync(0xFFFFFFFFu, s, off);
            int oa = __shfl_down_sync(0xFFFFFFFFu, am, off);
            if (om > m || (om == m && oa < am)) {
                s = os + s * expf(m - om);
                m = om;
                am = oa;
            } else {
                s = s + os * expf(om - m);
            }
        }
        if (lid == 0) {
            g_lse[t * BB + b] = m + logf(s);
            g_tok[b] = am;
        }
    }
}

// ---------------- final: subtract lse over the whole output ----------------
__global__ void k_norm(float* __restrict__ out) {
    size_t i = (size_t)blockIdx.x * 256 + threadIdx.x;  // float4 index
    const size_t per_b = (size_t)TT * VV / 4;  // 1,024,000
    if (i >= (size_t)BB * per_b) return;
    int b = (int)(i / per_b);
    size_t rem = i - (size_t)b * per_b;
    int t = (int)(rem / (VV / 4));
    float l = g_lse[t * BB + b];
    float4* p = (float4*)out + i;
    float4 v = *p;
    v.x -= l; v.y -= l; v.z -= l; v.w -= l;
    *p = v;
}

// ---------------- host ----------------
extern "C" void kernel_launch(void* const* d_in, const int* in_sizes, int n_in,
                              void* d_out, int out_size) {
    const int* toks = (const int*)d_in[0];
    const float* hidden = (const float*)d_in[1];
    const float* emb = (const float*)d_in[2];
    const float* w_ih_f = (const float*)d_in[3];
    const float* w_hh_f = (const float*)d_in[4];
    const float* b_ih_f = (const float*)d_in[5];
    const float* b_hh_f = (const float*)d_in[6];
    const float* w_ih_b = (const float*)d_in[7];
    const float* w_hh_b = (const float*)d_in[8];
    const float* b_ih_b = (const float*)d_in[9];
    const float* b_hh_b = (const float*)d_in[10];
    const float* w_out = (const float*)d_in[11];
    const float* b_out = (const float*)d_in[12];
    float* out = (float*)d_out;

    (void)in_sizes; (void)n_in; (void)out_size;

    k_transpose_out<<<dim3(1000, 64), 256>>>(w_out);
    k_transpose_gru<<<dim3(96, 32, 4), 256>>>(w_ih_f, w_hh_f, w_ih_b, w_hh_b);
    k_init<<<(2 * BB * HH + BB + 255) / 256, 256>>>(toks, hidden);

    for (int t = 0; t < TT; ++t) {
        k_gru_gemm<<<dim3(48, 4, 2), 256>>>(emb);
        k_gate<<<(2 * BB * HH) / 256, 256>>>(b_ih_f, b_hh_f, b_ih_b, b_hh_b);
        k_logits<<<125, 512>>>(b_out, out + (size_t)t * VV);
        k_smreduce<<<BB, 1024>>>(out + (size_t)t * VV, t);
    }
    k_norm<<<128000, 256>>>(out);
}

// round 15
// speedup vs baseline: 1.4457x; 1.2374x over previous
#include <cuda_runtime.h>
#include <cstdint>
#include <math.h>

#define BB 32
#define HH 1024
#define VV 32000
#define TT 128
#define KK2 2048          // 2H
#define NGATE 12288       // 4 * 3H
#define NTILES 125        // logits n-tiles of 256

// ---------------- device scratch (static, no allocations) ----------------
__device__ float g_xcat[BB * KK2];            // [b][0:1024]=h_f, [b][1024:2048]=h_b
__device__ float g_gpart[4 * BB * NGATE];     // [part][b][n]  coalesced for gate
__device__ int   g_tok[BB];                   // current decoder tokens
__device__ float g_lse[TT * BB];              // log-sum-exp per (t, b)
__device__ float g_wT[(size_t)2048 * 32000];  // w_out transposed: [(k>>1)][n][k&1]
__device__ float g_wgT[(size_t)4 * 1024 * 3072]; // GRU weights: [g][(k>>1)][n][k&1]
__device__ float g_pm[BB * 128];              // softmax partial max    [b][tile]
__device__ float g_ps[BB * 128];              // softmax partial sumexp [b][tile]
__device__ int   g_pa[BB * 128];              // softmax partial argmax [b][tile]

// ---------------- f32x2 helpers ----------------
__device__ __forceinline__ unsigned long long pk2(float a, float b) {
    unsigned long long r;
    asm("mov.b64 %0, {%1, %2};" : "=l"(r) : "f"(a), "f"(b));
    return r;
}
__device__ __forceinline__ float2 upk2(unsigned long long v) {
    float2 f;
    asm("mov.b64 {%0, %1}, %2;" : "=f"(f.x), "=f"(f.y) : "l"(v));
    return f;
}
__device__ __forceinline__ void fma2(unsigned long long& acc, unsigned long long a,
                                     unsigned long long x) {
    asm("fma.rn.f32x2 %0, %1, %2, %0;" : "+l"(acc) : "l"(a), "l"(x));
}

// ---------------- weight transposes (run once per launch, idempotent) ----------------
__global__ void k_transpose_out(const float* __restrict__ w_out) {
    __shared__ float tsm[32][33];
    const int nb = blockIdx.x * 32;
    const int kb = blockIdx.y * 32;
    const int tid = threadIdx.x;
    for (int i = tid; i < 1024; i += 256) {
        int kl = i & 31, nl = i >> 5;
        tsm[nl][kl] = w_out[(size_t)(nb + nl) * 2048 + kb + kl];
    }
    __syncthreads();
    float2* outp = (float2*)g_wT;
    for (int i = tid; i < 512; i += 256) {
        int nl = i & 31, kpl = i >> 5;
        outp[(size_t)((kb >> 1) + kpl) * 32000 + nb + nl] =
            make_float2(tsm[nl][2 * kpl], tsm[nl][2 * kpl + 1]);
    }
}

__global__ void k_transpose_gru(const float* __restrict__ w_ih_f, const float* __restrict__ w_hh_f,
                                const float* __restrict__ w_ih_b, const float* __restrict__ w_hh_b) {
    __shared__ float tsm[32][33];
    const int nb = blockIdx.x * 32;  // 0..3071
    const int kb = blockIdx.y * 32;  // 0..1023
    const int g = blockIdx.z;        // 0..3
    const float* W = (g == 0) ? w_ih_f : (g == 1) ? w_hh_f : (g == 2) ? w_ih_b : w_hh_b;
    const int tid = threadIdx.x;
    for (int i = tid; i < 1024; i += 256) {
        int kl = i & 31, nl = i >> 5;
        tsm[nl][kl] = W[(size_t)(nb + nl) * 1024 + kb + kl];
    }
    __syncthreads();
    float2* outp = (float2*)g_wgT + (size_t)g * 512 * 3072;
    for (int i = tid; i < 512; i += 256) {
        int nl = i & 31, kpl = i >> 5;
        outp[(size_t)((kb >> 1) + kpl) * 3072 + nb + nl] =
            make_float2(tsm[nl][2 * kpl], tsm[nl][2 * kpl + 1]);
    }
}

// ---------------- init: hidden -> g_xcat, tokens (int32/int64 autodetect) ----------------
__global__ void k_init(const int* __restrict__ toks_raw, const float* __restrict__ hidden) {
    int idx = blockIdx.x * blockDim.x + threadIdx.x;
    if (idx < 2 * BB * HH) {
        int c = idx / (BB * HH);
        int rem = idx - c * (BB * HH);
        int b = rem / HH;
        int j = rem - b * HH;
        g_xcat[b * KK2 + c * HH + j] = hidden[idx];
    } else if (idx < 2 * BB * HH + BB) {
        int b = idx - 2 * BB * HH;
        bool is64 = true;
        for (int i = 1; i < 32; i += 2)
            if (toks_raw[i] != 0) is64 = false;
        g_tok[b] = is64 ? toks_raw[2 * b] : toks_raw[b];
    }
}

// ---------------- GRU GEMM (embedding fused, batch-split) ----------------
// Grid (48 n-tiles, 4 k-parts, 2 batch-halves), 256 thr, occ 3.  [verified]
__global__ void __launch_bounds__(256, 3)
k_gru_gemm(const float* __restrict__ emb) {
    __shared__ float2 xs[2][8][128];  // 16 KB; reused for combine + tile

    const int tile = blockIdx.x;   // 0..47
    const int kpart = blockIdx.y;  // 0..3
    const int bs = blockIdx.z;     // 0..1 : batches [bs*16, bs*16+16)
    const int n_base = tile * 256;
    const int g = n_base / 3072;   // 0:ih_f 1:hh_f 2:ih_b 3:hh_b
    const int wrow_base = n_base % 3072;

    const int tid = threadIdx.x;
    const int w = tid >> 5, lane = tid & 31;
    const int ks = w >> 2, wn = w & 3;

    for (int i = tid; i < 2 * 8 * 128; i += 256) {
        int s = i >> 10;
        int rem = i & 1023;
        int p = rem >> 7;
        int k = rem & 127;
        int kg = kpart * 256 + s * 128 + k;
        int b0 = bs * 16 + 2 * p, b1 = b0 + 1;
        float v0, v1;
        if (g & 1) {
            int half = g >> 1;
            v0 = g_xcat[b0 * KK2 + half * HH + kg];
            v1 = g_xcat[b1 * KK2 + half * HH + kg];
        } else {
            v0 = emb[(size_t)g_tok[b0] * HH + kg];
            v1 = emb[(size_t)g_tok[b1] * HH + kg];
        }
        xs[s][p][k] = make_float2(v0, v1);
    }
    __syncthreads();

    const int n_local0 = wn * 64 + lane;
    unsigned long long acc[2][8];
#pragma unroll
    for (int i2 = 0; i2 < 2; ++i2)
#pragma unroll
        for (int p = 0; p < 8; ++p) acc[i2][p] = 0ULL;

    const float2* wp = (const float2*)g_wgT + (size_t)g * 512 * 3072 +
                       (size_t)(kpart * 128 + ks * 64) * 3072 + wrow_base + n_local0;
#pragma unroll 4
    for (int kp = 0; kp < 64; ++kp) {
        float2 a0 = wp[0];
        float2 a1 = wp[32];
        wp += 3072;
        unsigned long long w00 = pk2(a0.x, a0.x);
        unsigned long long w01 = pk2(a0.y, a0.y);
        unsigned long long w10 = pk2(a1.x, a1.x);
        unsigned long long w11 = pk2(a1.y, a1.y);
#pragma unroll
        for (int p = 0; p < 8; ++p) {
            ulonglong2 xv = *(const ulonglong2*)&xs[ks][p][2 * kp];
            fma2(acc[0][p], w00, xv.x);
            fma2(acc[0][p], w01, xv.y);
            fma2(acc[1][p], w10, xv.x);
            fma2(acc[1][p], w11, xv.y);
        }
    }

    __syncthreads();
    float2* csm = (float2*)xs;  // [16][128]
    if (tid >= 128) {
        int u = tid - 128;
#pragma unroll
        for (int i2 = 0; i2 < 2; ++i2)
#pragma unroll
            for (int p = 0; p < 8; ++p)
                csm[(i2 * 8 + p) * 128 + u] = upk2(acc[i2][p]);
    }
    __syncthreads();
    float2 res[2][8];
    if (tid < 128) {
#pragma unroll
        for (int i2 = 0; i2 < 2; ++i2)
#pragma unroll
            for (int p = 0; p < 8; ++p) {
                float2 a = upk2(acc[i2][p]);
                float2 c = csm[(i2 * 8 + p) * 128 + tid];
                res[i2][p] = make_float2(a.x + c.x, a.y + c.y);
            }
    }
    __syncthreads();
    float* tilep = (float*)xs;  // [16][256]
    if (tid < 128) {
#pragma unroll
        for (int i2 = 0; i2 < 2; ++i2) {
            int nl = n_local0 + i2 * 32;
#pragma unroll
            for (int p = 0; p < 8; ++p) {
                tilep[(2 * p) * 256 + nl] = res[i2][p].x;
                tilep[(2 * p + 1) * 256 + nl] = res[i2][p].y;
            }
        }
    }
    __syncthreads();
    float* dst = g_gpart + (size_t)kpart * BB * NGATE;
    for (int i = tid; i < 16 * 256; i += 256) {
        int bl = i >> 8;
        int nl = i & 255;
        dst[(size_t)(bs * 16 + bl) * NGATE + n_base + nl] = tilep[i];
    }
}

// ---------------- gate combine: update h_f / h_b in g_xcat ----------------
__device__ __forceinline__ float sigf(float x) { return 1.0f / (1.0f + expf(-x)); }
__device__ __forceinline__ float tanh_acc(float x) {
    float ax = fabsf(x);
    float t = expf(-2.0f * ax);
    float r = (1.0f - t) / (1.0f + t);
    return copysignf(r, x);
}
__device__ __forceinline__ float gsum(int row, int b) {
    return g_gpart[(size_t)0 * BB * NGATE + (size_t)b * NGATE + row] +
           g_gpart[(size_t)1 * BB * NGATE + (size_t)b * NGATE + row] +
           g_gpart[(size_t)2 * BB * NGATE + (size_t)b * NGATE + row] +
           g_gpart[(size_t)3 * BB * NGATE + (size_t)b * NGATE + row];
}
__global__ void k_gate(const float* __restrict__ b_ih_f, const float* __restrict__ b_hh_f,
                       const float* __restrict__ b_ih_b, const float* __restrict__ b_hh_b) {
    int idx = blockIdx.x * blockDim.x + threadIdx.x;  // 65536
    int c = idx >> 15;
    int b = (idx >> 10) & 31;
    int j = idx & 1023;
    const float* bih = c ? b_ih_b : b_ih_f;
    const float* bhh = c ? b_hh_b : b_hh_f;
    int base = c * 6144;
    float i_r = gsum(base + j, b)        + bih[j];
    float i_z = gsum(base + 1024 + j, b) + bih[1024 + j];
    float i_n = gsum(base + 2048 + j, b) + bih[2048 + j];
    float h_r = gsum(base + 3072 + j, b) + bhh[j];
    float h_z = gsum(base + 4096 + j, b) + bhh[1024 + j];
    float h_n = gsum(base + 5120 + j, b) + bhh[2048 + j];
    float r = sigf(i_r + h_r);
    float z = sigf(i_z + h_z);
    float nn = tanh_acc(i_n + r * h_n);
    float hp = g_xcat[b * KK2 + c * HH + j];
    g_xcat[b * KK2 + c * HH + j] = (1.0f - z) * nn + z * hp;
}

// ---------------- logits GEMM (round-10 exact + fused softmax partial tail) ----------------
// Grid (125 n-tiles of 256, 2 batch-halves), 256 thr, occ 2.
__global__ void __launch_bounds__(256, 2)
k_logits(const float* __restrict__ b_out, float* __restrict__ outp /* d_out + t*V */) {
    __shared__ float2 xs[2][8][128];  // 16 KB, reused for combine/tile

    const int tile = blockIdx.x;    // 0..124
    const int n_base = tile * 256;
    const int bs = blockIdx.y;      // 0..1 : batches [bs*16, bs*16+16)
    const int tid = threadIdx.x;
    const int w = tid >> 5, lane = tid & 31;
    const int ks = w >> 2, wn = w & 3;
    const int n_local0 = wn * 64 + lane;

    unsigned long long acc[2][8];
#pragma unroll
    for (int i2 = 0; i2 < 2; ++i2)
#pragma unroll
        for (int p = 0; p < 8; ++p) acc[i2][p] = 0ULL;

    for (int chunk = 0; chunk < 8; ++chunk) {
        __syncthreads();
        for (int i = tid; i < 2 * 8 * 128; i += 256) {
            int s = i >> 10;
            int rem = i & 1023;
            int p = rem >> 7;
            int k = rem & 127;
            int kg = s * 1024 + chunk * 128 + k;
            int b0 = bs * 16 + 2 * p, b1 = b0 + 1;
            xs[s][p][k] = make_float2(g_xcat[b0 * KK2 + kg], g_xcat[b1 * KK2 + kg]);
        }
        __syncthreads();

        const float2* wp = (const float2*)g_wT +
                           (size_t)(ks * 512 + chunk * 64) * 32000 + n_base + n_local0;
#pragma unroll 4
        for (int kp = 0; kp < 64; ++kp) {
            float2 a0 = wp[0];
            float2 a1 = wp[32];
            wp += 32000;
            unsigned long long w00 = pk2(a0.x, a0.x);
            unsigned long long w01 = pk2(a0.y, a0.y);
            unsigned long long w10 = pk2(a1.x, a1.x);
            unsigned long long w11 = pk2(a1.y, a1.y);
#pragma unroll
            for (int p = 0; p < 8; ++p) {
                ulonglong2 xv = *(const ulonglong2*)&xs[ks][p][2 * kp];
                fma2(acc[0][p], w00, xv.x);
                fma2(acc[0][p], w01, xv.y);
                fma2(acc[1][p], w10, xv.x);
                fma2(acc[1][p], w11, xv.y);
            }
        }
    }

    __syncthreads();
    float2* csm = (float2*)xs;  // [16][128]
    if (tid >= 128) {
        int u = tid - 128;
#pragma unroll
        for (int i2 = 0; i2 < 2; ++i2)
#pragma unroll
            for (int p = 0; p < 8; ++p)
                csm[(i2 * 8 + p) * 128 + u] = upk2(acc[i2][p]);
    }
    __syncthreads();
    float2 res[2][8];
    if (tid < 128) {
#pragma unroll
        for (int i2 = 0; i2 < 2; ++i2)
#pragma unroll
            for (int p = 0; p < 8; ++p) {
                float2 a = upk2(acc[i2][p]);
                float2 c = csm[(i2 * 8 + p) * 128 + tid];
                res[i2][p] = make_float2(a.x + c.x, a.y + c.y);
            }
    }
    __syncthreads();
    float* tilep = (float*)xs;  // [16][256]
    if (tid < 128) {
#pragma unroll
        for (int i2 = 0; i2 < 2; ++i2) {
            int nl = n_local0 + i2 * 32;
#pragma unroll
            for (int p = 0; p < 8; ++p) {
                tilep[(2 * p) * 256 + nl] = res[i2][p].x;
                tilep[(2 * p + 1) * 256 + nl] = res[i2][p].y;
            }
        }
    }
    __syncthreads();
    // global write with bias; keep biased value in the tile for the partial reduce
    for (int i = tid; i < 16 * 256; i += 256) {
        int bl = i >> 8;
        int nl = i & 255;
        int n = n_base + nl;
        float v = tilep[i] + b_out[n];
        outp[(size_t)(bs * 16 + bl) * ((size_t)TT * VV) + n] = v;
        tilep[i] = v;
    }
    __syncthreads();
    // per-batch online (max, argmax, sumexp) over this 256-col tile  [verified round 8]
    {
        int pb = tid >> 4;    // 0..15 local batch
        int sub = tid & 15;
        float m = -3.4e38f, s = 0.0f;
        int am = 0;
#pragma unroll
        for (int q = 0; q < 16; ++q) {
            int nl = sub + q * 16;
            float x = tilep[pb * 256 + nl];
            int n = n_base + nl;
            if (x > m) {
                s = s * expf(m - x) + 1.0f;
                m = x;
                am = n;
            } else {
                s += expf(x - m);
            }
        }
#pragma unroll
        for (int off = 8; off > 0; off >>= 1) {
            float om = __shfl_down_sync(0xFFFFFFFFu, m, off);
            float os = __shfl_down_sync(0xFFFFFFFFu, s, off);
            int oa = __shfl_down_sync(0xFFFFFFFFu, am, off);
            if (om > m || (om == m && oa < am)) {
                s = os + s * expf(m - om);
                m = om;
                am = oa;
            } else {
                s = s + os * expf(om - m);
            }
        }
        if (sub == 0) {
            int bg = bs * 16 + pb;
            g_pm[bg * 128 + tile] = m;
            g_ps[bg * 128 + tile] = s;
            g_pa[bg * 128 + tile] = am;
        }
    }
}

// ---------------- combine softmax partials -> g_lse, g_tok ----------------
__global__ void k_smreduce(int step) {
    const int b = blockIdx.x;     // 0..31
    const int tid = threadIdx.x;  // 128
    float m = -3.4e38f, s = 0.0f;
    int am = 0x7FFFFFFF;
    if (tid < NTILES) {
        m = g_pm[b * 128 + tid];
        s = g_ps[b * 128 + tid];
        am = g_pa[b * 128 + tid];
    }
#pragma unroll
    for (int off = 16; off > 0; off >>= 1) {
        float om = __shfl_down_sync(0xFFFFFFFFu, m, off);
        float os = __shfl_down_sync(0xFFFFFFFFu, s, off);
        int oa = __shfl_down_sync(0xFFFFFFFFu, am, off);
        if (om > m || (om == m && oa < am)) {
            s = os + s * expf(m - om);
            m = om;
            am = oa;
        } else {
            s = s + os * expf(om - m);
        }
    }
    __shared__ float smm[4], sms[4];
    __shared__ int sma[4];
    int wid = tid >> 5, lid = tid & 31;
    if (lid == 0) { smm[wid] = m; sms[wid] = s; sma[wid] = am; }
    __syncthreads();
    if (wid == 0) {
        if (lid < 4) { m = smm[lid]; s = sms[lid]; am = sma[lid]; }
        else { m = -3.4e38f; s = 0.0f; am = 0x7FFFFFFF; }
#pragma unroll
        for (int off = 2; off > 0; off >>= 1) {
            float om = __shfl_down_sync(0xFFFFFFFFu, m, off);
            float os = __shfl_down_sync(0xFFFFFFFFu, s, off);
            int oa = __shfl_down_sync(0xFFFFFFFFu, am, off);
            if (om > m || (om == m && oa < am)) {
                s = os + s * expf(m - om);
                m = om;
                am = oa;
            } else {
                s = s + os * expf(om - m);
            }
        }
        if (lid == 0) {
            g_lse[step * BB + b] = m + logf(s);
            g_tok[b] = am;
        }
    }
}

// ---------------- final: subtract lse over the whole output ----------------
__global__ void k_norm(float* __restrict__ out) {
    size_t i = (size_t)blockIdx.x * 256 + threadIdx.x;  // float4 index
    const size_t per_b = (size_t)TT * VV / 4;  // 1,024,000
    if (i >= (size_t)BB * per_b) return;
    int b = (int)(i / per_b);
    size_t rem = i - (size_t)b * per_b;
    int t = (int)(rem / (VV / 4));
    float l = g_lse[t * BB + b];
    float4* p = (float4*)out + i;
    float4 v = *p;
    v.x -= l; v.y -= l; v.z -= l; v.w -= l;
    *p = v;
}

// ---------------- host ----------------
extern "C" void kernel_launch(void* const* d_in, const int* in_sizes, int n_in,
                              void* d_out, int out_size) {
    const int* toks = (const int*)d_in[0];
    const float* hidden = (const float*)d_in[1];
    const float* emb = (const float*)d_in[2];
    const float* w_ih_f = (const float*)d_in[3];
    const float* w_hh_f = (const float*)d_in[4];
    const float* b_ih_f = (const float*)d_in[5];
    const float* b_hh_f = (const float*)d_in[6];
    const float* w_ih_b = (const float*)d_in[7];
    const float* w_hh_b = (const float*)d_in[8];
    const float* b_ih_b = (const float*)d_in[9];
    const float* b_hh_b = (const float*)d_in[10];
    const float* w_out = (const float*)d_in[11];
    const float* b_out = (const float*)d_in[12];
    float* out = (float*)d_out;

    (void)in_sizes; (void)n_in; (void)out_size;

    k_transpose_out<<<dim3(1000, 64), 256>>>(w_out);
    k_transpose_gru<<<dim3(96, 32, 4), 256>>>(w_ih_f, w_hh_f, w_ih_b, w_hh_b);
    k_init<<<(2 * BB * HH + BB + 255) / 256, 256>>>(toks, hidden);

    for (int t = 0; t < TT; ++t) {
        k_gru_gemm<<<dim3(48, 4, 2), 256>>>(emb);
        k_gate<<<(2 * BB * HH) / 256, 256>>>(b_ih_f, b_hh_f, b_ih_b, b_hh_b);
        k_logits<<<dim3(125, 2), 256>>>(b_out, out + (size_t)t * VV);
        k_smreduce<<<BB, 128>>>(t);
    }
    k_norm<<<128000, 256>>>(out);
}

// round 16
// speedup vs baseline: 1.4492x; 1.0024x over previous
#include <cuda_runtime.h>
#include <cstdint>
#include <math.h>

#define BB 32
#define HH 1024
#define VV 32000
#define TT 128
#define KK2 2048          // 2H
#define NGATE 12288       // 4 * 3H
#define NTILES 125        // logits n-tiles of 256

// ---------------- device scratch (static, no allocations) ----------------
__device__ float g_xcat[BB * KK2];            // [b][0:1024]=h_f, [b][1024:2048]=h_b
__device__ float g_gpart[4 * BB * NGATE];     // [part][b][n]  coalesced for gate
__device__ int   g_tok[BB];                   // current decoder tokens
__device__ float g_lse[TT * BB];              // log-sum-exp per (t, b)
__device__ float g_wT[(size_t)2048 * 32000];  // w_out transposed: [(k>>1)][n][k&1]
__device__ float g_wgT[(size_t)4 * 1024 * 3072]; // GRU weights: [g][(k>>1)][n][k&1]
__device__ float g_pm[BB * 128];              // softmax partial max    [b][tile]
__device__ float g_ps[BB * 128];              // softmax partial sumexp [b][tile]
__device__ int   g_pa[BB * 128];              // softmax partial argmax [b][tile]

// ---------------- f32x2 helpers ----------------
__device__ __forceinline__ unsigned long long pk2(float a, float b) {
    unsigned long long r;
    asm("mov.b64 %0, {%1, %2};" : "=l"(r) : "f"(a), "f"(b));
    return r;
}
__device__ __forceinline__ float2 upk2(unsigned long long v) {
    float2 f;
    asm("mov.b64 {%0, %1}, %2;" : "=f"(f.x), "=f"(f.y) : "l"(v));
    return f;
}
__device__ __forceinline__ void fma2(unsigned long long& acc, unsigned long long a,
                                     unsigned long long x) {
    asm("fma.rn.f32x2 %0, %1, %2, %0;" : "+l"(acc) : "l"(a), "l"(x));
}

// ---------------- weight transposes (run once per launch, idempotent) ----------------
__global__ void k_transpose_out(const float* __restrict__ w_out) {
    __shared__ float tsm[32][33];
    const int nb = blockIdx.x * 32;
    const int kb = blockIdx.y * 32;
    const int tid = threadIdx.x;
    for (int i = tid; i < 1024; i += 256) {
        int kl = i & 31, nl = i >> 5;
        tsm[nl][kl] = w_out[(size_t)(nb + nl) * 2048 + kb + kl];
    }
    __syncthreads();
    float2* outp = (float2*)g_wT;
    for (int i = tid; i < 512; i += 256) {
        int nl = i & 31, kpl = i >> 5;
        outp[(size_t)((kb >> 1) + kpl) * 32000 + nb + nl] =
            make_float2(tsm[nl][2 * kpl], tsm[nl][2 * kpl + 1]);
    }
}

__global__ void k_transpose_gru(const float* __restrict__ w_ih_f, const float* __restrict__ w_hh_f,
                                const float* __restrict__ w_ih_b, const float* __restrict__ w_hh_b) {
    __shared__ float tsm[32][33];
    const int nb = blockIdx.x * 32;  // 0..3071
    const int kb = blockIdx.y * 32;  // 0..1023
    const int g = blockIdx.z;        // 0..3
    const float* W = (g == 0) ? w_ih_f : (g == 1) ? w_hh_f : (g == 2) ? w_ih_b : w_hh_b;
    const int tid = threadIdx.x;
    for (int i = tid; i < 1024; i += 256) {
        int kl = i & 31, nl = i >> 5;
        tsm[nl][kl] = W[(size_t)(nb + nl) * 1024 + kb + kl];
    }
    __syncthreads();
    float2* outp = (float2*)g_wgT + (size_t)g * 512 * 3072;
    for (int i = tid; i < 512; i += 256) {
        int nl = i & 31, kpl = i >> 5;
        outp[(size_t)((kb >> 1) + kpl) * 3072 + nb + nl] =
            make_float2(tsm[nl][2 * kpl], tsm[nl][2 * kpl + 1]);
    }
}

// ---------------- init: hidden -> g_xcat, tokens (int32/int64 autodetect) ----------------
__global__ void k_init(const int* __restrict__ toks_raw, const float* __restrict__ hidden) {
    int idx = blockIdx.x * blockDim.x + threadIdx.x;
    if (idx < 2 * BB * HH) {
        int c = idx / (BB * HH);
        int rem = idx - c * (BB * HH);
        int b = rem / HH;
        int j = rem - b * HH;
        g_xcat[b * KK2 + c * HH + j] = hidden[idx];
    } else if (idx < 2 * BB * HH + BB) {
        int b = idx - 2 * BB * HH;
        bool is64 = true;
        for (int i = 1; i < 32; i += 2)
            if (toks_raw[i] != 0) is64 = false;
        g_tok[b] = is64 ? toks_raw[2 * b] : toks_raw[b];
    }
}

// ---------------- GRU GEMM (embedding fused, batch-split) ----------------
// Grid (48 n-tiles, 4 k-parts, 2 batch-halves), 256 thr, occ 3.  [verified]
__global__ void __launch_bounds__(256, 3)
k_gru_gemm(const float* __restrict__ emb) {
    __shared__ float2 xs[2][8][128];  // 16 KB; reused for combine + tile

    const int tile = blockIdx.x;   // 0..47
    const int kpart = blockIdx.y;  // 0..3
    const int bs = blockIdx.z;     // 0..1 : batches [bs*16, bs*16+16)
    const int n_base = tile * 256;
    const int g = n_base / 3072;   // 0:ih_f 1:hh_f 2:ih_b 3:hh_b
    const int wrow_base = n_base % 3072;

    const int tid = threadIdx.x;
    const int w = tid >> 5, lane = tid & 31;
    const int ks = w >> 2, wn = w & 3;

    for (int i = tid; i < 2 * 8 * 128; i += 256) {
        int s = i >> 10;
        int rem = i & 1023;
        int p = rem >> 7;
        int k = rem & 127;
        int kg = kpart * 256 + s * 128 + k;
        int b0 = bs * 16 + 2 * p, b1 = b0 + 1;
        float v0, v1;
        if (g & 1) {
            int half = g >> 1;
            v0 = g_xcat[b0 * KK2 + half * HH + kg];
            v1 = g_xcat[b1 * KK2 + half * HH + kg];
        } else {
            v0 = emb[(size_t)g_tok[b0] * HH + kg];
            v1 = emb[(size_t)g_tok[b1] * HH + kg];
        }
        xs[s][p][k] = make_float2(v0, v1);
    }
    __syncthreads();

    const int n_local0 = wn * 64 + lane;
    unsigned long long acc[2][8];
#pragma unroll
    for (int i2 = 0; i2 < 2; ++i2)
#pragma unroll
        for (int p = 0; p < 8; ++p) acc[i2][p] = 0ULL;

    const float2* wp = (const float2*)g_wgT + (size_t)g * 512 * 3072 +
                       (size_t)(kpart * 128 + ks * 64) * 3072 + wrow_base + n_local0;
#pragma unroll 4
    for (int kp = 0; kp < 64; ++kp) {
        float2 a0 = wp[0];
        float2 a1 = wp[32];
        wp += 3072;
        unsigned long long w00 = pk2(a0.x, a0.x);
        unsigned long long w01 = pk2(a0.y, a0.y);
        unsigned long long w10 = pk2(a1.x, a1.x);
        unsigned long long w11 = pk2(a1.y, a1.y);
#pragma unroll
        for (int p = 0; p < 8; ++p) {
            ulonglong2 xv = *(const ulonglong2*)&xs[ks][p][2 * kp];
            fma2(acc[0][p], w00, xv.x);
            fma2(acc[0][p], w01, xv.y);
            fma2(acc[1][p], w10, xv.x);
            fma2(acc[1][p], w11, xv.y);
        }
    }

    __syncthreads();
    float2* csm = (float2*)xs;  // [16][128]
    if (tid >= 128) {
        int u = tid - 128;
#pragma unroll
        for (int i2 = 0; i2 < 2; ++i2)
#pragma unroll
            for (int p = 0; p < 8; ++p)
                csm[(i2 * 8 + p) * 128 + u] = upk2(acc[i2][p]);
    }
    __syncthreads();
    float2 res[2][8];
    if (tid < 128) {
#pragma unroll
        for (int i2 = 0; i2 < 2; ++i2)
#pragma unroll
            for (int p = 0; p < 8; ++p) {
                float2 a = upk2(acc[i2][p]);
                float2 c = csm[(i2 * 8 + p) * 128 + tid];
                res[i2][p] = make_float2(a.x + c.x, a.y + c.y);
            }
    }
    __syncthreads();
    float* tilep = (float*)xs;  // [16][256]
    if (tid < 128) {
#pragma unroll
        for (int i2 = 0; i2 < 2; ++i2) {
            int nl = n_local0 + i2 * 32;
#pragma unroll
            for (int p = 0; p < 8; ++p) {
                tilep[(2 * p) * 256 + nl] = res[i2][p].x;
                tilep[(2 * p + 1) * 256 + nl] = res[i2][p].y;
            }
        }
    }
    __syncthreads();
    float* dst = g_gpart + (size_t)kpart * BB * NGATE;
    for (int i = tid; i < 16 * 256; i += 256) {
        int bl = i >> 8;
        int nl = i & 255;
        dst[(size_t)(bs * 16 + bl) * NGATE + n_base + nl] = tilep[i];
    }
}

// ---------------- gate combine: update h_f / h_b in g_xcat ----------------
__device__ __forceinline__ float sigf(float x) { return 1.0f / (1.0f + expf(-x)); }
__device__ __forceinline__ float tanh_acc(float x) {
    float ax = fabsf(x);
    float t = expf(-2.0f * ax);
    float r = (1.0f - t) / (1.0f + t);
    return copysignf(r, x);
}
__device__ __forceinline__ float gsum(int row, int b) {
    return g_gpart[(size_t)0 * BB * NGATE + (size_t)b * NGATE + row] +
           g_gpart[(size_t)1 * BB * NGATE + (size_t)b * NGATE + row] +
           g_gpart[(size_t)2 * BB * NGATE + (size_t)b * NGATE + row] +
           g_gpart[(size_t)3 * BB * NGATE + (size_t)b * NGATE + row];
}
__global__ void k_gate(const float* __restrict__ b_ih_f, const float* __restrict__ b_hh_f,
                       const float* __restrict__ b_ih_b, const float* __restrict__ b_hh_b) {
    int idx = blockIdx.x * blockDim.x + threadIdx.x;  // 65536
    int c = idx >> 15;
    int b = (idx >> 10) & 31;
    int j = idx & 1023;
    const float* bih = c ? b_ih_b : b_ih_f;
    const float* bhh = c ? b_hh_b : b_hh_f;
    int base = c * 6144;
    float i_r = gsum(base + j, b)        + bih[j];
    float i_z = gsum(base + 1024 + j, b) + bih[1024 + j];
    float i_n = gsum(base + 2048 + j, b) + bih[2048 + j];
    float h_r = gsum(base + 3072 + j, b) + bhh[j];
    float h_z = gsum(base + 4096 + j, b) + bhh[1024 + j];
    float h_n = gsum(base + 5120 + j, b) + bhh[2048 + j];
    float r = sigf(i_r + h_r);
    float z = sigf(i_z + h_z);
    float nn = tanh_acc(i_n + r * h_n);
    float hp = g_xcat[b * KK2 + c * HH + j];
    g_xcat[b * KK2 + c * HH + j] = (1.0f - z) * nn + z * hp;
}

// ---------------- logits GEMM (round-15 winner + double-buffered staging) ----------------
// Grid (125 n-tiles of 256, 2 batch-halves), 256 thr, occ 2.  ONE sync per chunk.
__global__ void __launch_bounds__(256, 2)
k_logits(const float* __restrict__ b_out, float* __restrict__ outp /* d_out + t*V */) {
    __shared__ float2 xs[2][2][8][128];  // [buf][ks][p][k] = 32 KB, reused for combine/tile

    const int tile = blockIdx.x;    // 0..124
    const int n_base = tile * 256;
    const int bs = blockIdx.y;      // 0..1 : batches [bs*16, bs*16+16)
    const int tid = threadIdx.x;
    const int w = tid >> 5, lane = tid & 31;
    const int ks = w >> 2, wn = w & 3;
    const int n_local0 = wn * 64 + lane;

    unsigned long long acc[2][8];
#pragma unroll
    for (int i2 = 0; i2 < 2; ++i2)
#pragma unroll
        for (int p = 0; p < 8; ++p) acc[i2][p] = 0ULL;

    // prologue: stage chunk 0 into buffer 0
#pragma unroll
    for (int q = 0; q < 8; ++q) {
        int i = tid + 256 * q;
        int s = i >> 10;
        int rem = i & 1023;
        int p = rem >> 7;
        int k = rem & 127;
        int kg = s * 1024 + k;
        int b0 = bs * 16 + 2 * p, b1 = b0 + 1;
        xs[0][s][p][k] = make_float2(g_xcat[b0 * KK2 + kg], g_xcat[b1 * KK2 + kg]);
    }
    __syncthreads();

    for (int chunk = 0; chunk < 8; ++chunk) {
        const int buf = chunk & 1;
        // prefetch next chunk into registers (LDGs in flight during compute)
        float va[8], vb[8];
        if (chunk < 7) {
#pragma unroll
            for (int q = 0; q < 8; ++q) {
                int i = tid + 256 * q;
                int s = i >> 10;
                int rem = i & 1023;
                int p = rem >> 7;
                int k = rem & 127;
                int kg = s * 1024 + (chunk + 1) * 128 + k;
                int b0 = bs * 16 + 2 * p;
                va[q] = g_xcat[b0 * KK2 + kg];
                vb[q] = g_xcat[(b0 + 1) * KK2 + kg];
            }
        }

        const float2* wp = (const float2*)g_wT +
                           (size_t)(ks * 512 + chunk * 64) * 32000 + n_base + n_local0;
#pragma unroll 4
        for (int kp = 0; kp < 64; ++kp) {
            float2 a0 = wp[0];
            float2 a1 = wp[32];
            wp += 32000;
            unsigned long long w00 = pk2(a0.x, a0.x);
            unsigned long long w01 = pk2(a0.y, a0.y);
            unsigned long long w10 = pk2(a1.x, a1.x);
            unsigned long long w11 = pk2(a1.y, a1.y);
#pragma unroll
            for (int p = 0; p < 8; ++p) {
                ulonglong2 xv = *(const ulonglong2*)&xs[buf][ks][p][2 * kp];
                fma2(acc[0][p], w00, xv.x);
                fma2(acc[0][p], w01, xv.y);
                fma2(acc[1][p], w10, xv.x);
                fma2(acc[1][p], w11, xv.y);
            }
        }

        // store prefetched chunk into the other buffer, then one barrier
        if (chunk < 7) {
#pragma unroll
            for (int q = 0; q < 8; ++q) {
                int i = tid + 256 * q;
                int s = i >> 10;
                int rem = i & 1023;
                int p = rem >> 7;
                int k = rem & 127;
                xs[buf ^ 1][s][p][k] = make_float2(va[q], vb[q]);
            }
            __syncthreads();
        }
    }

    __syncthreads();
    float2* csm = (float2*)xs;  // [16][128]
    if (tid >= 128) {
        int u = tid - 128;
#pragma unroll
        for (int i2 = 0; i2 < 2; ++i2)
#pragma unroll
            for (int p = 0; p < 8; ++p)
                csm[(i2 * 8 + p) * 128 + u] = upk2(acc[i2][p]);
    }
    __syncthreads();
    float2 res[2][8];
    if (tid < 128) {
#pragma unroll
        for (int i2 = 0; i2 < 2; ++i2)
#pragma unroll
            for (int p = 0; p < 8; ++p) {
                float2 a = upk2(acc[i2][p]);
                float2 c = csm[(i2 * 8 + p) * 128 + tid];
                res[i2][p] = make_float2(a.x + c.x, a.y + c.y);
            }
    }
    __syncthreads();
    float* tilep = (float*)xs;  // [16][256]
    if (tid < 128) {
#pragma unroll
        for (int i2 = 0; i2 < 2; ++i2) {
            int nl = n_local0 + i2 * 32;
#pragma unroll
            for (int p = 0; p < 8; ++p) {
                tilep[(2 * p) * 256 + nl] = res[i2][p].x;
                tilep[(2 * p + 1) * 256 + nl] = res[i2][p].y;
            }
        }
    }
    __syncthreads();
    // global write with bias; keep biased value in the tile for the partial reduce
    for (int i = tid; i < 16 * 256; i += 256) {
        int bl = i >> 8;
        int nl = i & 255;
        int n = n_base + nl;
        float v = tilep[i] + b_out[n];
        outp[(size_t)(bs * 16 + bl) * ((size_t)TT * VV) + n] = v;
        tilep[i] = v;
    }
    __syncthreads();
    // per-batch online (max, argmax, sumexp) over this 256-col tile  [verified]
    {
        int pb = tid >> 4;    // 0..15 local batch
        int sub = tid & 15;
        float m = -3.4e38f, s = 0.0f;
        int am = 0;
#pragma unroll
        for (int q = 0; q < 16; ++q) {
            int nl = sub + q * 16;
            float x = tilep[pb * 256 + nl];
            int n = n_base + nl;
            if (x > m) {
                s = s * expf(m - x) + 1.0f;
                m = x;
                am = n;
            } else {
                s += expf(x - m);
            }
        }
#pragma unroll
        for (int off = 8; off > 0; off >>= 1) {
            float om = __shfl_down_sync(0xFFFFFFFFu, m, off);
            float os = __shfl_down_sync(0xFFFFFFFFu, s, off);
            int oa = __shfl_down_sync(0xFFFFFFFFu, am, off);
            if (om > m || (om == m && oa < am)) {
                s = os + s * expf(m - om);
                m = om;
                am = oa;
            } else {
                s = s + os * expf(om - m);
            }
        }
        if (sub == 0) {
            int bg = bs * 16 + pb;
            g_pm[bg * 128 + tile] = m;
            g_ps[bg * 128 + tile] = s;
            g_pa[bg * 128 + tile] = am;
        }
    }
}

// ---------------- combine softmax partials -> g_lse, g_tok ----------------
__global__ void k_smreduce(int step) {
    const int b = blockIdx.x;     // 0..31
    const int tid = threadIdx.x;  // 128
    float m = -3.4e38f, s = 0.0f;
    int am = 0x7FFFFFFF;
    if (tid < NTILES) {
        m = g_pm[b * 128 + tid];
        s = g_ps[b * 128 + tid];
        am = g_pa[b * 128 + tid];
    }
#pragma unroll
    for (int off = 16; off > 0; off >>= 1) {
        float om = __shfl_down_sync(0xFFFFFFFFu, m, off);
        float os = __shfl_down_sync(0xFFFFFFFFu, s, off);
        int oa = __shfl_down_sync(0xFFFFFFFFu, am, off);
        if (om > m || (om == m && oa < am)) {
            s = os + s * expf(m - om);
            m = om;
            am = oa;
        } else {
            s = s + os * expf(om - m);
        }
    }
    __shared__ float smm[4], sms[4];
    __shared__ int sma[4];
    int wid = tid >> 5, lid = tid & 31;
    if (lid == 0) { smm[wid] = m; sms[wid] = s; sma[wid] = am; }
    __syncthreads();
    if (wid == 0) {
        if (lid < 4) { m = smm[lid]; s = sms[lid]; am = sma[lid]; }
        else { m = -3.4e38f; s = 0.0f; am = 0x7FFFFFFF; }
#pragma unroll
        for (int off = 2; off > 0; off >>= 1) {
            float om = __shfl_down_sync(0xFFFFFFFFu, m, off);
            float os = __shfl_down_sync(0xFFFFFFFFu, s, off);
            int oa = __shfl_down_sync(0xFFFFFFFFu, am, off);
            if (om > m || (om == m && oa < am)) {
                s = os + s * expf(m - om);
                m = om;
                am = oa;
            } else {
                s = s + os * expf(om - m);
            }
        }
        if (lid == 0) {
            g_lse[step * BB + b] = m + logf(s);
            g_tok[b] = am;
        }
    }
}

// ---------------- final: subtract lse over the whole output ----------------
__global__ void k_norm(float* __restrict__ out) {
    size_t i = (size_t)blockIdx.x * 256 + threadIdx.x;  // float4 index
    const size_t per_b = (size_t)TT * VV / 4;  // 1,024,000
    if (i >= (size_t)BB * per_b) return;
    int b = (int)(i / per_b);
    size_t rem = i - (size_t)b * per_b;
    int t = (int)(rem / (VV / 4));
    float l = g_lse[t * BB + b];
    float4* p = (float4*)out + i;
    float4 v = *p;
    v.x -= l; v.y -= l; v.z -= l; v.w -= l;
    *p = v;
}

// ---------------- host ----------------
extern "C" void kernel_launch(void* const* d_in, const int* in_sizes, int n_in,
                              void* d_out, int out_size) {
    const int* toks = (const int*)d_in[0];
    const float* hidden = (const float*)d_in[1];
    const float* emb = (const float*)d_in[2];
    const float* w_ih_f = (const float*)d_in[3];
    const float* w_hh_f = (const float*)d_in[4];
    const float* b_ih_f = (const float*)d_in[5];
    const float* b_hh_f = (const float*)d_in[6];
    const float* w_ih_b = (const float*)d_in[7];
    const float* w_hh_b = (const float*)d_in[8];
    const float* b_ih_b = (const float*)d_in[9];
    const float* b_hh_b = (const float*)d_in[10];
    const float* w_out = (const float*)d_in[11];
    const float* b_out = (const float*)d_in[12];
    float* out = (float*)d_out;

    (void)in_sizes; (void)n_in; (void)out_size;

    k_transpose_out<<<dim3(1000, 64), 256>>>(w_out);
    k_transpose_gru<<<dim3(96, 32, 4), 256>>>(w_ih_f, w_hh_f, w_ih_b, w_hh_b);
    k_init<<<(2 * BB * HH + BB + 255) / 256, 256>>>(toks, hidden);

    for (int t = 0; t < TT; ++t) {
        k_gru_gemm<<<dim3(48, 4, 2), 256>>>(emb);
        k_gate<<<(2 * BB * HH) / 256, 256>>>(b_ih_f, b_hh_f, b_ih_b, b_hh_b);
        k_logits<<<dim3(125, 2), 256>>>(b_out, out + (size_t)t * VV);
        k_smreduce<<<BB, 128>>>(t);
    }
    k_norm<<<128000, 256>>>(out);
}